// round 14
// baseline (speedup 1.0000x reference)
#include <cuda_runtime.h>
#include <cstdint>

#define BB 8
#define CC 32
#define FF 8
#define HH 128
#define WW 128
#define IHP 129
#define IWP 132                        // padded integral row stride (floats), 528 B
#define DSTR_W 164                     // words per D buffer (161 used: sigma(128)=160)
typedef unsigned long long ull;

// smem layout (floats): I | D buffers | T table
#define D_OFF_F (IHP*IWP)              // 17028
#define T_OFF_F (D_OFF_F + 16*2*DSTR_W)  // 22276
#define SMEM_FLOATS (T_OFF_F + 1024*4)   // 26372 floats = 105488 B

__device__ __forceinline__ ull pk2(float lo, float hi) {
    ull r; asm("mov.b64 %0, {%1, %2};" : "=l"(r) : "f"(lo), "f"(hi)); return r;
}
__device__ __forceinline__ void unpk2(float& lo, float& hi, ull v) {
    asm("mov.b64 {%0, %1}, %2;" : "=f"(lo), "=f"(hi) : "l"(v));
}
__device__ __forceinline__ ull ffma2(ull a, ull b, ull c) {
    ull r; asm("fma.rn.f32x2 %0, %1, %2, %3;" : "=l"(r) : "l"(a), "l"(b), "l"(c));
    return r;
}
__device__ __forceinline__ uint32_t smem_u32(const void* p) {
    uint32_t a;
    asm("{ .reg .u64 t; cvta.to.shared.u64 t, %1; cvt.u32.u64 %0, t; }"
        : "=r"(a) : "l"(p));
    return a;
}
// swizzled D byte address: word sigma(j) = j + (j>>2)
__device__ __forceinline__ uint32_t daddr(uint32_t dbase, int j) {
    return dbase + 4u * (uint32_t)(j + (j >> 2));
}

// ---------------------------------------------------------------------------
// Fused: one block per bc. Build integral + T table in smem, then 16 warps =
// (f, half), 64 h each: BUILD(h) -> syncwarp -> OUT(h), double-buffered D.
// ---------------------------------------------------------------------------
__global__ void __launch_bounds__(512, 2) boxconv_fused(
    const float* __restrict__ in,
    const float* __restrict__ xmn, const float* __restrict__ xmx,
    const float* __restrict__ ymn, const float* __restrict__ ymx,
    float* __restrict__ out)
{
    extern __shared__ float sm[];
    float*  I = sm;                                 // [IHP][IWP]
    float4* T = (float4*)(sm + T_OFF_F);            // [FF*HH]

    const int bc   = blockIdx.x;
    const int c    = bc % CC;
    const int tid  = threadIdx.x;
    const int wid  = tid >> 5;
    const int lane = tid & 31;

    // ---- T table: per (f,h) row byte-offsets + fractional weights ----------
    for (int e = tid; e < FF * HH; e += 512) {
        int fi = e >> 7, h = e & 127;
        int cfi = c * FF + fi;
        float xm = xmn[cfi] * 128.0f;
        float xM = xmx[cfi] * 128.0f;
        float u0 = fminf(fmaxf((float)h + xm, 0.0f), 128.0f);
        float u1 = fminf(fmaxf((float)h + xM + 1.0f, 0.0f), 128.0f);
        int i0 = min(max(h + (int)floorf(xm), 0), 127);
        int i1 = min(max(h + (int)floorf(xM + 1.0f), 0), 127);
        float4 t;
        t.x = __int_as_float(i0 * (IWP * 4));
        t.y = __int_as_float(i1 * (IWP * 4));
        t.z = u0 - (float)i0;
        t.w = u1 - (float)i1;
        T[e] = t;
    }

    // ---- Build I: row exclusive scans (warp wid -> rows 8w..8w+7) ----------
    if (tid < IWP) I[tid] = 0.0f;
    const float* img = in + (size_t)bc * (HH * WW);
#pragma unroll
    for (int r = 0; r < 8; ++r) {
        int row = wid * 8 + r;
        float4 cv = *(const float4*)(img + (size_t)row * WW + 4 * lane);
        float s4 = cv.x + cv.y + cv.z + cv.w;
        float x = __shfl_up_sync(0xffffffffu, s4, 1);
        if (lane == 0) x = 0.0f;
#pragma unroll
        for (int off = 1; off < 32; off <<= 1) {
            float t = __shfl_up_sync(0xffffffffu, x, off);
            if (lane >= off) x += t;
        }
        float4 o;
        o.x = x;
        o.y = x + cv.x;
        o.z = o.y + cv.y;
        o.w = o.z + cv.z;
        float* dst = I + (size_t)(row + 1) * IWP;
        *(float4*)(dst + 4 * lane) = o;
        if (lane == 31) {
            dst[128] = o.w + cv.w;
            dst[129] = 0.0f; dst[130] = 0.0f; dst[131] = 0.0f;
        }
    }
    __syncthreads();

    // ---- level 1: within-stripe inclusive column sums (8-row stripes) -------
    for (int g = lane; g < 33; g += 32) {
        float* col = I + 4 * g + (size_t)(8 * wid + 1) * IWP;
        float4 s = make_float4(0.f, 0.f, 0.f, 0.f);
#pragma unroll
        for (int r = 0; r < 8; ++r) {
            float4 v = *(float4*)(col + (size_t)r * IWP);
            s.x += v.x; s.y += v.y; s.z += v.z; s.w += v.w;
            *(float4*)(col + (size_t)r * IWP) = s;
        }
    }
    __syncthreads();

    // ---- level 2: per-warp stripe offsets in registers -----------------------
    float4 off_a = make_float4(0.f, 0.f, 0.f, 0.f);
    float4 off_b = make_float4(0.f, 0.f, 0.f, 0.f);
    for (int s = 0; s < wid; ++s) {
        const float4* tr = (const float4*)(I + (size_t)(8 * s + 8) * IWP);
        float4 v = tr[lane];
        off_a.x += v.x; off_a.y += v.y; off_a.z += v.z; off_a.w += v.w;
        if (lane == 0) {
            float4 v2 = tr[32];
            off_b.x += v2.x; off_b.y += v2.y; off_b.z += v2.z; off_b.w += v2.w;
        }
    }
    __syncthreads();

    // ---- level 3: add offsets -------------------------------------------------
    {
        float* colb = I + (size_t)(8 * wid + 1) * IWP;
#pragma unroll
        for (int r = 0; r < 8; ++r) {
            float4* p = (float4*)(colb + (size_t)r * IWP) + lane;
            float4 v = *p;
            v.x += off_a.x; v.y += off_a.y; v.z += off_a.z; v.w += off_a.w;
            *p = v;
            if (lane == 0) {
                float4* p2 = (float4*)(colb + (size_t)r * IWP) + 32;
                float4 v2 = *p2;
                v2.x += off_b.x; v2.y += off_b.y; v2.z += off_b.z; v2.w += off_b.w;
                *p2 = v2;
            }
        }
    }
    __syncthreads();

    // ======================= Phase C: warp = (f, half) =========================
    const int f    = wid & 7;
    const int half = wid >> 3;
    const int cf   = c * FF + f;

    const float ym  = __ldg(&ymn[cf]) * 128.0f;
    const float yM1 = __ldg(&ymx[cf]) * 128.0f + 1.0f;
    const int jc0  = (int)floorf(ym);
    const int jc1  = (int)floorf(yM1);

    const uint32_t sbase = smem_u32(sm);
    const uint32_t dbase = sbase + (uint32_t)(D_OFF_F * 4) + (uint32_t)wid * (2 * DSTR_W * 4);
    const uint32_t Ibase = sbase + 16u * (uint32_t)lane;

    // Gather window addresses (swizzled) + column weights (h-invariant).
    uint32_t A0[5], A1[5];
    float b0[4], b1[4];
    const int m0 = 4 * lane + jc0;
    const int m1 = 4 * lane + jc1;
#pragma unroll
    for (int i = 0; i < 5; ++i) {
        A0[i] = daddr(dbase, min(max(m0 + i, 0), 128));
        A1[i] = daddr(dbase, min(max(m1 + i, 0), 128));
    }
#pragma unroll
    for (int i = 0; i < 4; ++i) {
        float wv = (float)(4 * lane + i);
        float v0 = fminf(fmaxf(wv + ym,  0.0f), 128.0f);
        float v1 = fminf(fmaxf(wv + yM1, 0.0f), 128.0f);
        int ip0 = min(max(m0 + i, 0), 127);
        int ip1 = min(max(m1 + i, 0), 127);
        b0[i] = (m0 + i >= 128) ? 1.0f : (v0 - (float)ip0);
        b1[i] = (m1 + i >= 128) ? 1.0f : (v1 - (float)ip1);
    }

    const uint32_t dst0 = dbase + 20u * (uint32_t)lane;   // word 5*lane
    const ull M1v = pk2(-1.0f, -1.0f);
    const int h0 = half * 64;
    float* outc = out + ((size_t)(bc * FF + f) * HH + h0) * WW + 4 * lane;
    const float4* Tw = T + (f << 7) + h0;

#define LOADROW_S(BOFF, ra, rb, e)                                           \
    { uint32_t a_ = Ibase + (uint32_t)(BOFF);                                \
      float x0_, x1_, x2_, x3_;                                              \
      asm("ld.shared.v4.f32 {%0,%1,%2,%3}, [%4];"                            \
          : "=f"(x0_), "=f"(x1_), "=f"(x2_), "=f"(x3_) : "r"(a_));           \
      ra = pk2(x0_, x1_); rb = pk2(x2_, x3_);                                \
      uint32_t ae_ = sbase + (uint32_t)(BOFF) + 512u;                        \
      asm("ld.shared.f32 %0, [%1];" : "=f"(e) : "r"(ae_)); }

    // rolling window registers (row byte-offsets po0, po0+528, po1, po1+528)
    ull r00a, r00b, r01a, r01b, r10a, r10b, r11a, r11b;
    float e00, e01, e10, e11;
    int po0, po1;
    {
        float4 tv = Tw[0];
        po0 = __float_as_int(tv.x) - 528;    // bias: first ITER advances
        po1 = __float_as_int(tv.y) - 528;
        LOADROW_S(po0 + 528, r01a, r01b, e01);
        LOADROW_S(po1 + 528, r11a, r11b, e11);
        r00a = r01a; r00b = r01b; e00 = e01;
        r10a = r11a; r10b = r11b; e10 = e11;
    }

#define ITER(SUB, SOFF)                                                      \
    {                                                                        \
        float4 tv = Tw[hh + (SUB)];                                          \
        int off0 = __float_as_int(tv.x);                                     \
        int off1 = __float_as_int(tv.y);                                     \
        float a0 = tv.z, a1 = tv.w;                                          \
        ull nq0a, nq0b, nq1a, nq1b; float ne01, ne11;                        \
        LOADROW_S(off0 + 528, nq0a, nq0b, ne01);                             \
        LOADROW_S(off1 + 528, nq1a, nq1b, ne11);                             \
        bool adv0 = (off0 != po0);                                           \
        bool adv1 = (off1 != po1);                                           \
        r00a = adv0 ? r01a : r00a;                                           \
        r00b = adv0 ? r01b : r00b;                                           \
        e00  = adv0 ? e01  : e00;                                            \
        r10a = adv1 ? r11a : r10a;                                           \
        r10b = adv1 ? r11b : r10b;                                           \
        e10  = adv1 ? e11  : e10;                                            \
        r01a = nq0a; r01b = nq0b; e01 = ne01;                                \
        r11a = nq1a; r11b = nq1b; e11 = ne11;                                \
        po0 = off0; po1 = off1;                                              \
        ull a0v = pk2(a0, a0), a1v = pk2(a1, a1);                            \
        ull g0a = ffma2(a0v, ffma2(r00a, M1v, r01a), r00a);                  \
        ull g0b = ffma2(a0v, ffma2(r00b, M1v, r01b), r00b);                  \
        ull g1a = ffma2(a1v, ffma2(r10a, M1v, r11a), r10a);                  \
        ull g1b = ffma2(a1v, ffma2(r10b, M1v, r11b), r10b);                  \
        ull da = ffma2(g0a, M1v, g1a);                                       \
        ull db = ffma2(g0b, M1v, g1b);                                       \
        float d0_, d1_, d2_, d3_;                                            \
        unpk2(d0_, d1_, da); unpk2(d2_, d3_, db);                            \
        asm volatile("st.shared.f32 [%0+0+"  #SOFF "], %1;"                  \
                     :: "r"(dst0), "f"(d0_) : "memory");                     \
        asm volatile("st.shared.f32 [%0+4+"  #SOFF "], %1;"                  \
                     :: "r"(dst0), "f"(d1_) : "memory");                     \
        asm volatile("st.shared.f32 [%0+8+"  #SOFF "], %1;"                  \
                     :: "r"(dst0), "f"(d2_) : "memory");                     \
        asm volatile("st.shared.f32 [%0+12+" #SOFF "], %1;"                  \
                     :: "r"(dst0), "f"(d3_) : "memory");                     \
        float ge0 = fmaf(a0, e01 - e00, e00);                                \
        float ge1 = fmaf(a1, e11 - e10, e10);                                \
        if (lane == 0)                                                       \
            asm volatile("st.shared.f32 [%0+640+" #SOFF "], %1;"             \
                         :: "r"(dbase), "f"(ge1 - ge0) : "memory");          \
        __syncwarp();                                                        \
        float w0_[5], w1_[5];                                                \
        _Pragma("unroll")                                                    \
        for (int i = 0; i < 5; ++i) {                                        \
            asm volatile("ld.shared.f32 %0, [%1+" #SOFF "];"                 \
                         : "=f"(w0_[i]) : "r"(A0[i]));                       \
            asm volatile("ld.shared.f32 %0, [%1+" #SOFF "];"                 \
                         : "=f"(w1_[i]) : "r"(A1[i]));                       \
        }                                                                    \
        float4 o;                                                            \
        o.x = fmaf(b1[0], w1_[1] - w1_[0], w1_[0])                           \
            - fmaf(b0[0], w0_[1] - w0_[0], w0_[0]);                          \
        o.y = fmaf(b1[1], w1_[2] - w1_[1], w1_[1])                           \
            - fmaf(b0[1], w0_[2] - w0_[1], w0_[1]);                          \
        o.z = fmaf(b1[2], w1_[3] - w1_[2], w1_[2])                           \
            - fmaf(b0[2], w0_[3] - w0_[2], w0_[2]);                          \
        o.w = fmaf(b1[3], w1_[4] - w1_[3], w1_[3])                           \
            - fmaf(b0[3], w0_[4] - w0_[3], w0_[3]);                          \
        *(float4*)(outc + (size_t)(hh + (SUB)) * WW) = o;                    \
    }

    for (int hh = 0; hh < 64; hh += 2) {
        ITER(0, 0)
        ITER(1, 656)
    }
#undef ITER
#undef LOADROW_S
}

// ---------------------------------------------------------------------------
extern "C" void kernel_launch(void* const* d_in, const int* in_sizes, int n_in,
                              void* d_out, int out_size) {
    const float* input = (const float*)d_in[0];
    const float* x_min = (const float*)d_in[1];
    const float* x_max = (const float*)d_in[2];
    const float* y_min = (const float*)d_in[3];
    const float* y_max = (const float*)d_in[4];
    float* out = (float*)d_out;

    static int configured = 0;
    const int smem_bytes = SMEM_FLOATS * sizeof(float);   // 105488 B
    if (!configured) {
        cudaFuncSetAttribute(boxconv_fused,
                             cudaFuncAttributeMaxDynamicSharedMemorySize,
                             smem_bytes);
        configured = 1;
    }

    boxconv_fused<<<BB * CC, 512, smem_bytes>>>(
        input, x_min, x_max, y_min, y_max, out);
}

// round 15
// speedup vs baseline: 1.1659x; 1.1659x over previous
#include <cuda_runtime.h>
#include <cstdint>

#define BB 8
#define CC 32
#define FF 8
#define HH 128
#define WW 128
#define IHP 129
#define IWP 132                        // row stride (words): 3 pads + cols 0..128
#define DSTR_W 164                     // words per D buffer (161 used: sigma(128)=160)
typedef unsigned long long ull;

// smem: I (17028 f) + 16 warps * 2 buffers * DSTR_W
#define D_OFF_F (IHP*IWP)
#define SMEM_FLOATS (D_OFF_F + 16*2*DSTR_W)   // 22276 floats = 89104 B

__device__ __forceinline__ ull pk2(float lo, float hi) {
    ull r; asm("mov.b64 %0, {%1, %2};" : "=l"(r) : "f"(lo), "f"(hi)); return r;
}
__device__ __forceinline__ void unpk2(float& lo, float& hi, ull v) {
    asm("mov.b64 {%0, %1}, %2;" : "=f"(lo), "=f"(hi) : "l"(v));
}
__device__ __forceinline__ ull ffma2(ull a, ull b, ull c) {
    ull r; asm("fma.rn.f32x2 %0, %1, %2, %3;" : "=l"(r) : "l"(a), "l"(b), "l"(c));
    return r;
}
__device__ __forceinline__ uint32_t smem_u32(const void* p) {
    uint32_t a;
    asm("{ .reg .u64 t; cvta.to.shared.u64 t, %1; cvt.u32.u64 %0, t; }"
        : "=r"(a) : "l"(p));
    return a;
}
// swizzled D byte address: word sigma(j) = j + (j>>2)
__device__ __forceinline__ uint32_t daddr(uint32_t dbase, int j) {
    return dbase + 4u * (uint32_t)(j + (j >> 2));
}

// ---------------------------------------------------------------------------
// Fused: one block per bc. Shifted-inclusive integral layout (col j at word
// 3+j) so lane 31's v4 load carries col 128 — no separate e-column handling.
// 16 warps = (f, half), 64 h each: BUILD -> syncwarp -> OUT, double-buffered.
// ---------------------------------------------------------------------------
__global__ void __launch_bounds__(512, 2) boxconv_fused(
    const float* __restrict__ in,
    const float* __restrict__ xmn, const float* __restrict__ xmx,
    const float* __restrict__ ymn, const float* __restrict__ ymx,
    float* __restrict__ out)
{
    extern __shared__ float sm[];
    float* I = sm;                                  // [IHP][IWP] shifted layout

    const int bc   = blockIdx.x;
    const int c    = bc % CC;
    const int tid  = threadIdx.x;
    const int wid  = tid >> 5;
    const int lane = tid & 31;

    // ---- Build I: row INCLUSIVE scans (warp wid -> rows 8w..8w+7) ----------
    if (tid < IWP) I[tid] = 0.0f;                   // integral row 0 = zeros
    const float* img = in + (size_t)bc * (HH * WW);
#pragma unroll
    for (int r = 0; r < 8; ++r) {
        int row = wid * 8 + r;
        float4 cv = *(const float4*)(img + (size_t)row * WW + 4 * lane);
        float s4 = cv.x + cv.y + cv.z + cv.w;
        float x = __shfl_up_sync(0xffffffffu, s4, 1);
        if (lane == 0) x = 0.0f;
#pragma unroll
        for (int off = 1; off < 32; off <<= 1) {
            float t = __shfl_up_sync(0xffffffffu, x, off);
            if (lane >= off) x += t;
        }
        // inclusive sums at cols 4l+1..4l+4
        float4 o;
        o.x = x + cv.x;
        o.y = o.x + cv.y;
        o.z = o.y + cv.z;
        o.w = o.z + cv.w;
        char* dst = (char*)(I + (size_t)(row + 1) * IWP);
        *(float4*)(dst + 16 + 16 * lane) = o;       // words 4+4l .. 7+4l
        if (lane == 0)
            *(float4*)dst = make_float4(0.f, 0.f, 0.f, 0.f);  // pads + col0
    }
    __syncthreads();

    // ---- level 1: within-stripe inclusive column sums (8-row stripes) -------
    for (int g = lane; g < 33; g += 32) {
        float* col = I + 4 * g + (size_t)(8 * wid + 1) * IWP;
        float4 s = make_float4(0.f, 0.f, 0.f, 0.f);
#pragma unroll
        for (int r = 0; r < 8; ++r) {
            float4 v = *(float4*)(col + (size_t)r * IWP);
            s.x += v.x; s.y += v.y; s.z += v.z; s.w += v.w;
            *(float4*)(col + (size_t)r * IWP) = s;
        }
    }
    __syncthreads();

    // ---- level 2: per-warp stripe offsets in registers -----------------------
    float4 off_a = make_float4(0.f, 0.f, 0.f, 0.f);
    float4 off_b = make_float4(0.f, 0.f, 0.f, 0.f);
    for (int s = 0; s < wid; ++s) {
        const float4* tr = (const float4*)(I + (size_t)(8 * s + 8) * IWP);
        float4 v = tr[lane];
        off_a.x += v.x; off_a.y += v.y; off_a.z += v.z; off_a.w += v.w;
        if (lane == 0) {
            float4 v2 = tr[32];
            off_b.x += v2.x; off_b.y += v2.y; off_b.z += v2.z; off_b.w += v2.w;
        }
    }
    __syncthreads();

    // ---- level 3: add offsets -------------------------------------------------
    {
        float* colb = I + (size_t)(8 * wid + 1) * IWP;
#pragma unroll
        for (int r = 0; r < 8; ++r) {
            float4* p = (float4*)(colb + (size_t)r * IWP) + lane;
            float4 v = *p;
            v.x += off_a.x; v.y += off_a.y; v.z += off_a.z; v.w += off_a.w;
            *p = v;
            if (lane == 0) {
                float4* p2 = (float4*)(colb + (size_t)r * IWP) + 32;
                float4 v2 = *p2;
                v2.x += off_b.x; v2.y += off_b.y; v2.z += off_b.z; v2.w += off_b.w;
                *p2 = v2;
            }
        }
    }
    __syncthreads();

    // ======================= Phase C: warp = (f, half) =========================
    const int f    = wid & 7;
    const int half = wid >> 3;
    const int cf   = c * FF + f;

    const float xm  = __ldg(&xmn[cf]) * 128.0f;
    const float xM1 = __ldg(&xmx[cf]) * 128.0f + 1.0f;
    const float ym  = __ldg(&ymn[cf]) * 128.0f;
    const float yM1 = __ldg(&ymx[cf]) * 128.0f + 1.0f;
    const int icx0 = (int)floorf(xm);
    const int icx1 = (int)floorf(xM1);
    const int jc0  = (int)floorf(ym);
    const int jc1  = (int)floorf(yM1);

    const uint32_t sbase = smem_u32(sm);
    const uint32_t dbase = sbase + (uint32_t)(D_OFF_F * 4) + (uint32_t)wid * (2 * DSTR_W * 4);
    const uint32_t Ibase = sbase + 16u + 16u * (uint32_t)lane;  // cols 4l+1..4l+4

    // Gather window addresses (swizzled) + column weights (h-invariant).
    uint32_t A0[5], A1[5];
    float b0[4], b1[4];
    const int m0 = 4 * lane + jc0;
    const int m1 = 4 * lane + jc1;
#pragma unroll
    for (int i = 0; i < 5; ++i) {
        A0[i] = daddr(dbase, min(max(m0 + i, 0), 128));
        A1[i] = daddr(dbase, min(max(m1 + i, 0), 128));
    }
#pragma unroll
    for (int i = 0; i < 4; ++i) {
        float wv = (float)(4 * lane + i);
        float v0 = fminf(fmaxf(wv + ym,  0.0f), 128.0f);
        float v1 = fminf(fmaxf(wv + yM1, 0.0f), 128.0f);
        int ip0 = min(max(m0 + i, 0), 127);
        int ip1 = min(max(m1 + i, 0), 127);
        b0[i] = (m0 + i >= 128) ? 1.0f : (v0 - (float)ip0);
        b1[i] = (m1 + i >= 128) ? 1.0f : (v1 - (float)ip1);
    }

    // D store addresses: lane l writes D[4l+1..4l+4] -> words 5l+{1,2,3,5}
    const uint32_t dst0 = dbase + 20u * (uint32_t)lane;
    const ull M1v = pk2(-1.0f, -1.0f);
    const int h0 = half * 64;
    float* outc = out + ((size_t)(bc * FF + f) * HH + h0) * WW + 4 * lane;

    // Pre-seed D[0] = 0 in both buffers (never written by BUILD; always 0).
    if (lane == 0) {
        asm volatile("st.shared.f32 [%0], %1;" :: "r"(dbase), "f"(0.0f) : "memory");
        asm volatile("st.shared.f32 [%0+656], %1;" :: "r"(dbase), "f"(0.0f) : "memory");
    }

#define LOADROW_S(ROW, ra, rb)                                               \
    { uint32_t a_ = Ibase + (uint32_t)(ROW) * 528u;                          \
      float x0_, x1_, x2_, x3_;                                              \
      asm("ld.shared.v4.f32 {%0,%1,%2,%3}, [%4];"                            \
          : "=f"(x0_), "=f"(x1_), "=f"(x2_), "=f"(x3_) : "r"(a_));           \
      ra = pk2(x0_, x1_); rb = pk2(x2_, x3_); }

    // rolling window registers (rows pi0, pi0+1, pi1, pi1+1)
    ull r00a, r00b, r01a, r01b, r10a, r10b, r11a, r11b;
    int pi0 = min(max(h0 + icx0, 0), 127) - 1;   // bias: first ITER advances
    int pi1 = min(max(h0 + icx1, 0), 127) - 1;
    LOADROW_S(pi0 + 1, r01a, r01b);
    LOADROW_S(pi1 + 1, r11a, r11b);
    r00a = r01a; r00b = r01b;
    r10a = r11a; r10b = r11b;

#define ITER(SUB, SOFF)                                                      \
    {                                                                        \
        const int h = h0 + hh + (SUB);                                       \
        int i0 = min(max(h + icx0, 0), 127);                                 \
        int i1 = min(max(h + icx1, 0), 127);                                 \
        ull nq0a, nq0b, nq1a, nq1b;                                          \
        LOADROW_S(i0 + 1, nq0a, nq0b);                                       \
        LOADROW_S(i1 + 1, nq1a, nq1b);                                       \
        bool adv0 = (i0 != pi0);                                             \
        bool adv1 = (i1 != pi1);                                             \
        r00a = adv0 ? r01a : r00a;                                           \
        r00b = adv0 ? r01b : r00b;                                           \
        r10a = adv1 ? r11a : r10a;                                           \
        r10b = adv1 ? r11b : r10b;                                           \
        r01a = nq0a; r01b = nq0b;                                            \
        r11a = nq1a; r11b = nq1b;                                            \
        pi0 = i0; pi1 = i1;                                                  \
        float u0 = fminf(fmaxf((float)h + xm,  0.0f), 128.0f);               \
        float u1 = fminf(fmaxf((float)h + xM1, 0.0f), 128.0f);               \
        float a0 = u0 - (float)i0;                                           \
        float a1 = u1 - (float)i1;                                           \
        ull a0v = pk2(a0, a0), a1v = pk2(a1, a1);                            \
        ull g0a = ffma2(a0v, ffma2(r00a, M1v, r01a), r00a);                  \
        ull g0b = ffma2(a0v, ffma2(r00b, M1v, r01b), r00b);                  \
        ull g1a = ffma2(a1v, ffma2(r10a, M1v, r11a), r10a);                  \
        ull g1b = ffma2(a1v, ffma2(r10b, M1v, r11b), r10b);                  \
        ull da = ffma2(g0a, M1v, g1a);                                       \
        ull db = ffma2(g0b, M1v, g1b);                                       \
        float d0_, d1_, d2_, d3_;                                            \
        unpk2(d0_, d1_, da); unpk2(d2_, d3_, db);                            \
        asm volatile("st.shared.f32 [%0+4+"  #SOFF "], %1;"                  \
                     :: "r"(dst0), "f"(d0_) : "memory");                     \
        asm volatile("st.shared.f32 [%0+8+"  #SOFF "], %1;"                  \
                     :: "r"(dst0), "f"(d1_) : "memory");                     \
        asm volatile("st.shared.f32 [%0+12+" #SOFF "], %1;"                  \
                     :: "r"(dst0), "f"(d2_) : "memory");                     \
        asm volatile("st.shared.f32 [%0+20+" #SOFF "], %1;"                  \
                     :: "r"(dst0), "f"(d3_) : "memory");                     \
        __syncwarp();                                                        \
        float w0_[5], w1_[5];                                                \
        _Pragma("unroll")                                                    \
        for (int i = 0; i < 5; ++i) {                                        \
            asm volatile("ld.shared.f32 %0, [%1+" #SOFF "];"                 \
                         : "=f"(w0_[i]) : "r"(A0[i]));                       \
            asm volatile("ld.shared.f32 %0, [%1+" #SOFF "];"                 \
                         : "=f"(w1_[i]) : "r"(A1[i]));                       \
        }                                                                    \
        float4 o;                                                            \
        o.x = fmaf(b1[0], w1_[1] - w1_[0], w1_[0])                           \
            - fmaf(b0[0], w0_[1] - w0_[0], w0_[0]);                          \
        o.y = fmaf(b1[1], w1_[2] - w1_[1], w1_[1])                           \
            - fmaf(b0[1], w0_[2] - w0_[1], w0_[1]);                          \
        o.z = fmaf(b1[2], w1_[3] - w1_[2], w1_[2])                           \
            - fmaf(b0[2], w0_[3] - w0_[2], w0_[2]);                          \
        o.w = fmaf(b1[3], w1_[4] - w1_[3], w1_[3])                           \
            - fmaf(b0[3], w0_[4] - w0_[3], w0_[3]);                          \
        *(float4*)(outc + (size_t)(hh + (SUB)) * WW) = o;                    \
    }

    for (int hh = 0; hh < 64; hh += 2) {
        ITER(0, 0)
        ITER(1, 656)
    }
#undef ITER
#undef LOADROW_S
}

// ---------------------------------------------------------------------------
extern "C" void kernel_launch(void* const* d_in, const int* in_sizes, int n_in,
                              void* d_out, int out_size) {
    const float* input = (const float*)d_in[0];
    const float* x_min = (const float*)d_in[1];
    const float* x_max = (const float*)d_in[2];
    const float* y_min = (const float*)d_in[3];
    const float* y_max = (const float*)d_in[4];
    float* out = (float*)d_out;

    static int configured = 0;
    const int smem_bytes = SMEM_FLOATS * sizeof(float);   // 89104 B
    if (!configured) {
        cudaFuncSetAttribute(boxconv_fused,
                             cudaFuncAttributeMaxDynamicSharedMemorySize,
                             smem_bytes);
        configured = 1;
    }

    boxconv_fused<<<BB * CC, 512, smem_bytes>>>(
        input, x_min, x_max, y_min, y_max, out);
}